// round 1
// baseline (speedup 1.0000x reference)
#include <cuda_runtime.h>
#include <math.h>

#define B_      64
#define L_      2048
#define DTS     8
#define DSEQ    120
#define DIN     128
#define H_      64
#define NSPLIT  8
#define SPLIT_LEN (L_ / NSPLIT)   // 256
#define TILE    32
#define TPB     128
#define XS      132               // padded x row stride (bank-conflict avoidance)
#define SLOPE   0.2291666666666667f   // (1/8 + 1/3)/2

// Scratch (device globals: allocation-free rule)
__device__ float g_qlast[B_ * H_];
__device__ float g_m[B_ * NSPLIT];
__device__ float g_s[B_ * NSPLIT];
__device__ float g_acc[B_ * NSPLIT * H_];

// ---------------------------------------------------------------------------
// Kernel 1: q_last[b][h] = rrelu(x[b, len-1] @ Wq + bq)
// ---------------------------------------------------------------------------
__global__ void qlast_kernel(const float* __restrict__ ts,
                             const float* __restrict__ seq,
                             const int*   __restrict__ lengths,
                             const float* __restrict__ Wq,
                             const float* __restrict__ bq) {
    int b = blockIdx.x;
    int l = lengths[b] - 1;
    __shared__ float sx[DIN];
    int t = threadIdx.x;
    if (t < DIN) {
        sx[t] = (t < DTS) ? ts[((size_t)b * L_ + l) * DTS + t]
                          : seq[((size_t)b * L_ + l) * DSEQ + (t - DTS)];
    }
    __syncthreads();
    if (t < H_) {
        float acc = bq[t];
#pragma unroll 8
        for (int d = 0; d < DIN; ++d) acc += sx[d] * Wq[d * H_ + t];
        g_qlast[b * H_ + t] = (acc >= 0.f) ? acc : acc * SLOPE;
    }
}

// ---------------------------------------------------------------------------
// Kernel 2: fused K/V projection + online softmax (split over L).
// Grid: (NSPLIT, B). Block: 128 threads.
// Thread (tg, hg): tg = tid>>4 (8 token groups of 4), hg = tid&15 (16 head
// groups of 4). Each thread computes 4 tokens x 4 heads for K and V.
// ---------------------------------------------------------------------------
__global__ void __launch_bounds__(TPB, 2)
fused_kv_attn(const float* __restrict__ ts,
              const float* __restrict__ seq,
              const int*   __restrict__ lengths,
              const float* __restrict__ Wk, const float* __restrict__ bk,
              const float* __restrict__ Wv, const float* __restrict__ bv) {
    int b   = blockIdx.y;
    int sp  = blockIdx.x;
    int len = lengths[b];
    int start = sp * SPLIT_LEN;
    int tid = threadIdx.x;
    int idx = b * NSPLIT + sp;

    if (start >= len) {
        // nothing valid in this split: write neutral partials
        if (tid == 0) { g_m[idx] = -INFINITY; g_s[idx] = 0.f; }
        if (tid < H_) g_acc[idx * H_ + tid] = 0.f;
        return;
    }

    extern __shared__ float sm[];
    float* sWk    = sm;                        // 8192 floats
    float* sWv    = sWk + DIN * H_;            // 8192 floats
    float* sX     = sWv + DIN * H_;            // TILE*XS = 4224
    float* sScore = sX + TILE * XS;            // 32
    float* sMS    = sScore + TILE;             // m, s, scale
    float* sRed   = sMS + 4;                   // 8*64 = 512

    // Cooperative W load (coalesced float4): 2048 float4 per matrix.
    {
        const float4* wk4 = (const float4*)Wk;
        const float4* wv4 = (const float4*)Wv;
        float4* swk4 = (float4*)sWk;
        float4* swv4 = (float4*)sWv;
#pragma unroll
        for (int i = 0; i < (DIN * H_ / 4) / TPB; ++i) {
            swk4[tid + i * TPB] = wk4[tid + i * TPB];
            swv4[tid + i * TPB] = wv4[tid + i * TPB];
        }
    }
    if (tid == 0) { sMS[0] = -INFINITY; sMS[1] = 0.f; }

    int hg = tid & 15;
    int tg = tid >> 4;
    int hbase = hg * 4;

    float bkr[4], bvr[4], qr[4];
#pragma unroll
    for (int i = 0; i < 4; ++i) {
        bkr[i] = bk[hbase + i];
        bvr[i] = bv[hbase + i];
        qr[i]  = g_qlast[b * H_ + hbase + i];
    }

    float accO[4] = {0.f, 0.f, 0.f, 0.f};

    int nvalid = min(SPLIT_LEN, len - start);
    int ntiles = (nvalid + TILE - 1) / TILE;

    __syncthreads();  // W load + sMS init visible

    for (int tile = 0; tile < ntiles; ++tile) {
        int tbase = start + tile * TILE;

        // ---- load x tile [TILE][DIN] into sX (coalesced from global) ----
        const float4* tsrc = (const float4*)(ts  + ((size_t)b * L_ + tbase) * DTS);
        const float4* ssrc = (const float4*)(seq + ((size_t)b * L_ + tbase) * DSEQ);
        if (tid < 64) {  // ts: 32 rows * 8 floats = 64 float4
            float4 v = tsrc[tid];
            int t = tid >> 1, c = (tid & 1) * 4;
            *(float4*)&sX[t * XS + c] = v;
        }
#pragma unroll
        for (int i = 0; i < 8; ++i) {  // seq: 32 rows * 30 float4 = 960
            int j = tid + i * TPB;
            if (j < 960) {
                float4 v = ssrc[j];
                int t = j / 30, c = j % 30;
                *(float4*)&sX[t * XS + DTS + c * 4] = v;
            }
        }
        __syncthreads();

        // ---- K and V register-blocked GEMM: 4 tokens x 4 heads each ----
        float kacc[4][4], vacc[4][4];
#pragma unroll
        for (int j = 0; j < 4; ++j)
#pragma unroll
            for (int i = 0; i < 4; ++i) { kacc[j][i] = 0.f; vacc[j][i] = 0.f; }

        const float* xb = sX + (tg * 4) * XS;
#pragma unroll 8
        for (int d = 0; d < DIN; ++d) {
            float xs[4];
            xs[0] = xb[d];
            xs[1] = xb[XS + d];
            xs[2] = xb[2 * XS + d];
            xs[3] = xb[3 * XS + d];
            float4 wk = *(const float4*)(sWk + d * H_ + hbase);
            float4 wv = *(const float4*)(sWv + d * H_ + hbase);
            float wks[4] = {wk.x, wk.y, wk.z, wk.w};
            float wvs[4] = {wv.x, wv.y, wv.z, wv.w};
#pragma unroll
            for (int j = 0; j < 4; ++j)
#pragma unroll
                for (int i = 0; i < 4; ++i) {
                    kacc[j][i] += xs[j] * wks[i];
                    vacc[j][i] += xs[j] * wvs[i];
                }
        }

        // bias + rrelu; partial scores over this thread's 4 heads
        float ps[4];
#pragma unroll
        for (int j = 0; j < 4; ++j) {
            float p = 0.f;
#pragma unroll
            for (int i = 0; i < 4; ++i) {
                float kk = kacc[j][i] + bkr[i];
                kk = (kk >= 0.f) ? kk : kk * SLOPE;
                p += qr[i] * kk;
                float vv = vacc[j][i] + bvr[i];
                vacc[j][i] = (vv >= 0.f) ? vv : vv * SLOPE;
            }
            ps[j] = p;
        }
        // reduce scores over 16 head-group lanes
#pragma unroll
        for (int off = 8; off >= 1; off >>= 1)
#pragma unroll
            for (int j = 0; j < 4; ++j)
                ps[j] += __shfl_xor_sync(0xffffffffu, ps[j], off);
        if (hg == 0) {
#pragma unroll
            for (int j = 0; j < 4; ++j) {
                int l = tbase + tg * 4 + j;
                sScore[tg * 4 + j] = (l < len) ? ps[j] : -INFINITY;
            }
        }
        __syncthreads();

        // ---- online softmax update (warp 0) ----
        if (tid < 32) {
            float sc = sScore[tid];
            float mt = sc;
#pragma unroll
            for (int off = 16; off >= 1; off >>= 1)
                mt = fmaxf(mt, __shfl_xor_sync(0xffffffffu, mt, off));
            float mold = sMS[0];
            float mnew = fmaxf(mold, mt);
            float scale = expf(mold - mnew);  // mold=-inf -> 0
            float w = expf(sc - mnew);        // sc=-inf   -> 0
            float wsum = w;
#pragma unroll
            for (int off = 16; off >= 1; off >>= 1)
                wsum += __shfl_xor_sync(0xffffffffu, wsum, off);
            sScore[tid] = w;
            if (tid == 0) {
                sMS[0] = mnew;
                sMS[1] = sMS[1] * scale + wsum;
                sMS[2] = scale;
            }
        }
        __syncthreads();

        // ---- accumulate weighted V ----
        float scale = sMS[2];
#pragma unroll
        for (int i = 0; i < 4; ++i) accO[i] *= scale;
#pragma unroll
        for (int j = 0; j < 4; ++j) {
            float w = sScore[tg * 4 + j];
#pragma unroll
            for (int i = 0; i < 4; ++i) accO[i] += w * vacc[j][i];
        }
        __syncthreads();  // protect sX/sScore before next tile
    }

    // ---- reduce accO over the 8 token groups ----
#pragma unroll
    for (int i = 0; i < 4; ++i) sRed[tg * H_ + hbase + i] = accO[i];
    __syncthreads();
    if (tid < H_) {
        float a = 0.f;
#pragma unroll
        for (int g = 0; g < 8; ++g) a += sRed[g * H_ + tid];
        g_acc[idx * H_ + tid] = a;
    }
    if (tid == 0) { g_m[idx] = sMS[0]; g_s[idx] = sMS[1]; }
}

// ---------------------------------------------------------------------------
// Kernel 3: combine the NSPLIT partial softmaxes per batch
// ---------------------------------------------------------------------------
__global__ void combine_kernel(float* __restrict__ out) {
    int b = blockIdx.x;
    int h = threadIdx.x;
    float M = -INFINITY;
#pragma unroll
    for (int i = 0; i < NSPLIT; ++i) M = fmaxf(M, g_m[b * NSPLIT + i]);
    float S = 0.f, A = 0.f;
#pragma unroll
    for (int i = 0; i < NSPLIT; ++i) {
        float e = expf(g_m[b * NSPLIT + i] - M);  // -inf -> 0
        S += g_s[b * NSPLIT + i] * e;
        A += g_acc[(b * NSPLIT + i) * H_ + h] * e;
    }
    out[b * H_ + h] = A / S;
}

// ---------------------------------------------------------------------------
extern "C" void kernel_launch(void* const* d_in, const int* in_sizes, int n_in,
                              void* d_out, int out_size) {
    const float* ts      = (const float*)d_in[0];
    const float* seq     = (const float*)d_in[1];
    const int*   lengths = (const int*)  d_in[2];
    const float* Wk      = (const float*)d_in[3];
    const float* bk      = (const float*)d_in[4];
    const float* Wq      = (const float*)d_in[5];
    const float* bq      = (const float*)d_in[6];
    const float* Wv      = (const float*)d_in[7];
    const float* bv      = (const float*)d_in[8];
    float* out = (float*)d_out;

    qlast_kernel<<<B_, 128>>>(ts, seq, lengths, Wq, bq);

    size_t smem = (size_t)(DIN * H_ * 2 + TILE * XS + TILE + 4 + 8 * H_) * sizeof(float);
    cudaFuncSetAttribute(fused_kv_attn,
                         cudaFuncAttributeMaxDynamicSharedMemorySize, (int)smem);
    dim3 grid(NSPLIT, B_);
    fused_kv_attn<<<grid, TPB, smem>>>(ts, seq, lengths, Wk, bk, Wv, bv);

    combine_kernel<<<B_, H_>>>(out);
}

// round 3
// speedup vs baseline: 1.6865x; 1.6865x over previous
#include <cuda_runtime.h>
#include <cuda_bf16.h>
#include <cstdint>
#include <math.h>

#define B_      64
#define L_      2048
#define DTS     8
#define DSEQ    120
#define DIN     128
#define H_      64
#define NSPLIT  16
#define TILE_M  128
#define TPB     256
#define SLOPE   0.2291666666666667f

// smem layout (bytes): header 4096, then 4 x 32KB bf16 tiles
#define HDR     4096
#define XH_OFF  (HDR + 0)
#define XL_OFF  (HDR + 32768)
#define WH_OFF  (HDR + 65536)
#define WL_OFF  (HDR + 98304)
#define SMEM_TOTAL (HDR + 131072)

__device__ float g_m[B_ * NSPLIT];
__device__ float g_s[B_ * NSPLIT];
__device__ float g_acc[B_ * NSPLIT * H_];
// pre-split weights, [hi/lo][k=128][n=128] bf16, n = [Wk cols | Wv cols]
__device__ __align__(16) uint16_t g_Wbf[2][DIN * DIN];

__device__ __forceinline__ uint32_t smem_u32(const void* p) {
    uint32_t a;
    asm("{ .reg .u64 t; cvta.to.shared.u64 t, %1; cvt.u32.u64 %0, t; }" : "=r"(a) : "l"(p));
    return a;
}
__device__ __forceinline__ float rrelu(float x) { return x >= 0.f ? x : x * SLOPE; }

// split (f0,f1) into bf16x2 hi + bf16x2 lo (packed b32)
__device__ __forceinline__ void cvt_hilo(float f0, float f1, uint32_t& h, uint32_t& l) {
    __nv_bfloat162 hh = __floats2bfloat162_rn(f0, f1);
    float r0 = f0 - __bfloat162float(hh.x);
    float r1 = f1 - __bfloat162float(hh.y);
    __nv_bfloat162 ll = __floats2bfloat162_rn(r0, r1);
    h = *reinterpret_cast<uint32_t*>(&hh);
    l = *reinterpret_cast<uint32_t*>(&ll);
}

#define LDSM_X4(r0, r1, r2, r3, addr) \
    asm volatile("ldmatrix.sync.aligned.m8n8.x4.shared.b16 {%0,%1,%2,%3}, [%4];" \
        : "=r"(r0), "=r"(r1), "=r"(r2), "=r"(r3) : "r"(addr))
#define LDSM_X4_T(r0, r1, r2, r3, addr) \
    asm volatile("ldmatrix.sync.aligned.m8n8.x4.trans.shared.b16 {%0,%1,%2,%3}, [%4];" \
        : "=r"(r0), "=r"(r1), "=r"(r2), "=r"(r3) : "r"(addr))

__device__ __forceinline__ void mma_bf16(float (&c)[4], uint32_t a0, uint32_t a1,
                                         uint32_t a2, uint32_t a3,
                                         uint32_t b0, uint32_t b1) {
    asm volatile(
        "mma.sync.aligned.m16n8k16.row.col.f32.bf16.bf16.f32 "
        "{%0,%1,%2,%3}, {%4,%5,%6,%7}, {%8,%9}, {%0,%1,%2,%3};"
        : "+f"(c[0]), "+f"(c[1]), "+f"(c[2]), "+f"(c[3])
        : "r"(a0), "r"(a1), "r"(a2), "r"(a3), "r"(b0), "r"(b1));
}

// ---------------------------------------------------------------------------
// prep: split [Wk|Wv] -> bf16 hi/lo, row-major [k][n]
// grid 8, block 256: j indexes (k, 8-col chunk)
// ---------------------------------------------------------------------------
__global__ void prep_kernel(const float* __restrict__ Wk, const float* __restrict__ Wv) {
    int j = blockIdx.x * blockDim.x + threadIdx.x;   // 0..2047
    int k = j >> 4, ch = j & 15;
    int n0 = ch * 8;
    const float* src = (n0 < H_) ? (Wk + k * H_ + n0) : (Wv + k * H_ + n0 - H_);
    float4 f0 = ((const float4*)src)[0];
    float4 f1 = ((const float4*)src)[1];
    uint32_t h[4], l[4];
    cvt_hilo(f0.x, f0.y, h[0], l[0]);
    cvt_hilo(f0.z, f0.w, h[1], l[1]);
    cvt_hilo(f1.x, f1.y, h[2], l[2]);
    cvt_hilo(f1.z, f1.w, h[3], l[3]);
    ((uint4*)&g_Wbf[0][k * DIN + n0])[0] = make_uint4(h[0], h[1], h[2], h[3]);
    ((uint4*)&g_Wbf[1][k * DIN + n0])[0] = make_uint4(l[0], l[1], l[2], l[3]);
}

// ---------------------------------------------------------------------------
// fused: per (split, batch) block — 128-token tile
// GEMM [128 x 128] x [128 x 128] via mma.sync bf16 3-pass, then scores,
// softmax, weighted V — all from register fragments.
// ---------------------------------------------------------------------------
__global__ void __launch_bounds__(TPB, 1)
fused_attn(const float* __restrict__ ts, const float* __restrict__ seq,
           const int* __restrict__ lengths,
           const float* __restrict__ bk,
           const float* __restrict__ Wq, const float* __restrict__ bq,
           const float* __restrict__ bv) {
    int b   = blockIdx.y;
    int sp  = blockIdx.x;
    int len = lengths[b];
    int start = sp * TILE_M;
    int tid = threadIdx.x;
    int wid = tid >> 5, lane = tid & 31;
    int idx = b * NSPLIT + sp;

    if (start >= len) {
        if (tid < H_) g_acc[idx * H_ + tid] = 0.f;
        if (tid == 0) { g_m[idx] = -INFINITY; g_s[idx] = 0.f; }
        return;
    }

    extern __shared__ char smem[];
    uint32_t sb = smem_u32(smem);
    float* sQ     = (float*)smem;            // 64
    float* sScore = (float*)(smem + 256);    // 128
    float* sBias  = (float*)(smem + 768);    // 128
    float* sXlast = (float*)(smem + 1280);   // 128
    float* sRed   = (float*)(smem + 1792);   // 8*64

    // ---- bias + last-token row ----
    if (tid < DIN) {
        sBias[tid] = (tid < H_) ? bk[tid] : bv[tid - H_];
        int l = len - 1;
        sXlast[tid] = (tid < DTS) ? ts[((size_t)b * L_ + l) * DTS + tid]
                                  : seq[((size_t)b * L_ + l) * DSEQ + (tid - DTS)];
    }

    // ---- X tile: fp32 -> bf16 hi/lo, swizzled [row][chunk^row&7] ----
#pragma unroll
    for (int it = 0; it < 8; ++it) {
        int j = tid + it * TPB;               // 0..2047
        int row = j >> 4, ch = j & 15;
        int token = start + row;
        const float* src = (ch == 0)
            ? (ts + ((size_t)b * L_ + token) * DTS)
            : (seq + ((size_t)b * L_ + token) * DSEQ + (ch * 8 - 8));
        float4 f0 = ((const float4*)src)[0];
        float4 f1 = ((const float4*)src)[1];
        uint32_t h[4], l[4];
        cvt_hilo(f0.x, f0.y, h[0], l[0]);
        cvt_hilo(f0.z, f0.w, h[1], l[1]);
        cvt_hilo(f1.x, f1.y, h[2], l[2]);
        cvt_hilo(f1.z, f1.w, h[3], l[3]);
        uint32_t off = (uint32_t)(row * 256 + ((ch ^ (row & 7)) << 4));
        *(uint4*)(smem + XH_OFF + off) = make_uint4(h[0], h[1], h[2], h[3]);
        *(uint4*)(smem + XL_OFF + off) = make_uint4(l[0], l[1], l[2], l[3]);
    }

    // ---- W tiles: copy pre-split bf16 from global, apply swizzle ----
#pragma unroll
    for (int it = 0; it < 16; ++it) {
        int j = tid + it * TPB;               // 0..4095
        int mat = j >> 11;
        int row = (j >> 4) & 127, ch = j & 15;
        uint4 v = ((const uint4*)g_Wbf[mat])[row * 16 + ch];
        uint32_t off = (uint32_t)(row * 256 + ((ch ^ (row & 7)) << 4));
        *(uint4*)(smem + (mat ? WL_OFF : WH_OFF) + off) = v;
    }
    __syncthreads();

    // ---- q = rrelu(x_last @ Wq + bq): 4 threads per h ----
    {
        int h = tid >> 2, part = tid & 3;
        float s = 0.f;
        const float* wq = Wq + part * 32 * H_ + h;
#pragma unroll 8
        for (int d = 0; d < 32; ++d) s += sXlast[part * 32 + d] * wq[d * H_];
        s += __shfl_xor_sync(0xffffffffu, s, 1);
        s += __shfl_xor_sync(0xffffffffu, s, 2);
        if (part == 0) sQ[h] = rrelu(s + bq[h]);
    }
    __syncthreads();

    // ---- GEMM: warp owns rows [16*wid, 16*wid+16), all 128 cols ----
    float acc[16][4];
#pragma unroll
    for (int n = 0; n < 16; ++n)
#pragma unroll
        for (int i = 0; i < 4; ++i) acc[n][i] = 0.f;

    int li = lane >> 3, lr = lane & 7;
    int roff = ((li & 1) << 3) + lr;          // 0..15 row offset within 16
    int ci   = li >> 1;                       // chunk sub-index 0/1
    int rm   = roff & 7;                      // swizzle key (rows 16-aligned)
    uint32_t xh_row = sb + XH_OFF + (uint32_t)((wid * 16 + roff) * 256);
    uint32_t xl_row = xh_row + (XL_OFF - XH_OFF);

#pragma unroll
    for (int ks = 0; ks < 8; ++ks) {
        uint32_t aoff = (uint32_t)((((2 * ks + ci) ^ rm)) << 4);
        uint32_t ah0, ah1, ah2, ah3, al0, al1, al2, al3;
        LDSM_X4(ah0, ah1, ah2, ah3, xh_row + aoff);
        LDSM_X4(al0, al1, al2, al3, xl_row + aoff);
        uint32_t wh_row = sb + WH_OFF + (uint32_t)((ks * 16 + roff) * 256);
        uint32_t wl_row = wh_row + (WL_OFF - WH_OFF);
#pragma unroll
        for (int ntp = 0; ntp < 8; ++ntp) {
            uint32_t boff = (uint32_t)((((2 * ntp + ci) ^ rm)) << 4);
            uint32_t bh0, bh1, bh2, bh3, bl0, bl1, bl2, bl3;
            LDSM_X4_T(bh0, bh1, bh2, bh3, wh_row + boff);
            LDSM_X4_T(bl0, bl1, bl2, bl3, wl_row + boff);
            mma_bf16(acc[2 * ntp],     ah0, ah1, ah2, ah3, bh0, bh1);
            mma_bf16(acc[2 * ntp + 1], ah0, ah1, ah2, ah3, bh2, bh3);
            mma_bf16(acc[2 * ntp],     ah0, ah1, ah2, ah3, bl0, bl1);
            mma_bf16(acc[2 * ntp + 1], ah0, ah1, ah2, ah3, bl2, bl3);
            mma_bf16(acc[2 * ntp],     al0, al1, al2, al3, bh0, bh1);
            mma_bf16(acc[2 * ntp + 1], al0, al1, al2, al3, bh2, bh3);
        }
    }

    // fragment coordinates: lane holds rows g, g+8; cols 8*nt + 2t, +1
    int g = lane >> 2, t = lane & 3;
    int r0 = wid * 16 + g, r1 = r0 + 8;

    // ---- K epilogue: scores for this warp's 16 rows ----
    {
        float s0 = 0.f, s1 = 0.f;
#pragma unroll
        for (int nt = 0; nt < 8; ++nt) {
            int c0 = 8 * nt + 2 * t, c1 = c0 + 1;
            float q0 = sQ[c0], q1 = sQ[c1];
            float b0 = sBias[c0], b1 = sBias[c1];
            s0 += q0 * rrelu(acc[nt][0] + b0) + q1 * rrelu(acc[nt][1] + b1);
            s1 += q0 * rrelu(acc[nt][2] + b0) + q1 * rrelu(acc[nt][3] + b1);
        }
        s0 += __shfl_xor_sync(0xffffffffu, s0, 1);
        s0 += __shfl_xor_sync(0xffffffffu, s0, 2);
        s1 += __shfl_xor_sync(0xffffffffu, s1, 1);
        s1 += __shfl_xor_sync(0xffffffffu, s1, 2);
        if (t == 0) {
            sScore[r0] = (start + r0 < len) ? s0 : -INFINITY;
            sScore[r1] = (start + r1 < len) ? s1 : -INFINITY;
        }
    }
    __syncthreads();

    // ---- softmax over the 128 scores (warp 0) ----
    if (wid == 0) {
        float v0 = sScore[lane], v1 = sScore[lane + 32];
        float v2 = sScore[lane + 64], v3 = sScore[lane + 96];
        float mx = fmaxf(fmaxf(v0, v1), fmaxf(v2, v3));
#pragma unroll
        for (int o = 16; o >= 1; o >>= 1)
            mx = fmaxf(mx, __shfl_xor_sync(0xffffffffu, mx, o));
        float e0 = __expf(v0 - mx), e1 = __expf(v1 - mx);
        float e2 = __expf(v2 - mx), e3 = __expf(v3 - mx);
        float sum = e0 + e1 + e2 + e3;
#pragma unroll
        for (int o = 16; o >= 1; o >>= 1)
            sum += __shfl_xor_sync(0xffffffffu, sum, o);
        sScore[lane] = e0; sScore[lane + 32] = e1;
        sScore[lane + 64] = e2; sScore[lane + 96] = e3;
        if (lane == 0) { g_m[idx] = mx; g_s[idx] = sum; }
    }
    __syncthreads();

    // ---- V epilogue: out[c] += w[m] * rrelu(V[m][c]) ----
    {
        float w0 = sScore[r0], w1 = sScore[r1];
#pragma unroll
        for (int nt = 0; nt < 8; ++nt) {
            int c0 = 8 * nt + 2 * t, c1 = c0 + 1;   // local V col (0..63)
            float b0 = sBias[64 + c0], b1 = sBias[64 + c1];
            float p0 = w0 * rrelu(acc[8 + nt][0] + b0) + w1 * rrelu(acc[8 + nt][2] + b0);
            float p1 = w0 * rrelu(acc[8 + nt][1] + b1) + w1 * rrelu(acc[8 + nt][3] + b1);
            p0 += __shfl_xor_sync(0xffffffffu, p0, 4);
            p0 += __shfl_xor_sync(0xffffffffu, p0, 8);
            p0 += __shfl_xor_sync(0xffffffffu, p0, 16);
            p1 += __shfl_xor_sync(0xffffffffu, p1, 4);
            p1 += __shfl_xor_sync(0xffffffffu, p1, 8);
            p1 += __shfl_xor_sync(0xffffffffu, p1, 16);
            if (g == 0) {
                sRed[wid * 64 + c0] = p0;
                sRed[wid * 64 + c1] = p1;
            }
        }
    }
    __syncthreads();

    if (tid < H_) {
        float a = 0.f;
#pragma unroll
        for (int w = 0; w < 8; ++w) a += sRed[w * 64 + tid];
        g_acc[idx * H_ + tid] = a;
    }
}

// ---------------------------------------------------------------------------
__global__ void combine_kernel(float* __restrict__ out) {
    int b = blockIdx.x;
    int h = threadIdx.x;
    float M = -INFINITY;
#pragma unroll
    for (int i = 0; i < NSPLIT; ++i) M = fmaxf(M, g_m[b * NSPLIT + i]);
    float S = 0.f, A = 0.f;
#pragma unroll
    for (int i = 0; i < NSPLIT; ++i) {
        float e = __expf(g_m[b * NSPLIT + i] - M);
        S += g_s[b * NSPLIT + i] * e;
        A += g_acc[(b * NSPLIT + i) * H_ + h] * e;
    }
    out[b * H_ + h] = A / S;
}

// ---------------------------------------------------------------------------
extern "C" void kernel_launch(void* const* d_in, const int* in_sizes, int n_in,
                              void* d_out, int out_size) {
    const float* ts      = (const float*)d_in[0];
    const float* seq     = (const float*)d_in[1];
    const int*   lengths = (const int*)  d_in[2];
    const float* Wk      = (const float*)d_in[3];
    const float* bk      = (const float*)d_in[4];
    const float* Wq      = (const float*)d_in[5];
    const float* bq      = (const float*)d_in[6];
    const float* Wv      = (const float*)d_in[7];
    const float* bv      = (const float*)d_in[8];
    float* out = (float*)d_out;

    static int configured = 0;
    if (!configured) {
        cudaFuncSetAttribute(fused_attn,
                             cudaFuncAttributeMaxDynamicSharedMemorySize, SMEM_TOTAL);
        configured = 1;
    }

    prep_kernel<<<8, TPB>>>(Wk, Wv);
    dim3 grid(NSPLIT, B_);
    fused_attn<<<grid, TPB, SMEM_TOTAL>>>(ts, seq, lengths, bk, Wq, bq, bv);
    combine_kernel<<<B_, H_>>>(out);
}

// round 4
// speedup vs baseline: 2.2394x; 1.3279x over previous
#include <cuda_runtime.h>
#include <cuda_fp16.h>
#include <cstdint>
#include <math.h>

#define B_      64
#define L_      2048
#define DTS     8
#define DSEQ    120
#define DIN     128
#define H_      64
#define NSPLIT  16
#define TILE_M  128
#define TPB     256
#define SLOPE   0.2291666666666667f

// smem layout (bytes): header 4KB, then XH, XL, WH tiles (32KB each)
#define HDR     4096
#define XH_OFF  (HDR + 0)
#define XL_OFF  (HDR + 32768)
#define WH_OFF  (HDR + 65536)
#define SMEM_TOTAL (HDR + 98304)   // 102400 B -> 2 blocks/SM

__device__ float g_m[B_ * NSPLIT];
__device__ float g_s[B_ * NSPLIT];
__device__ float g_acc[B_ * NSPLIT * H_];

__device__ __forceinline__ uint32_t smem_u32(const void* p) {
    uint32_t a;
    asm("{ .reg .u64 t; cvta.to.shared.u64 t, %1; cvt.u32.u64 %0, t; }" : "=r"(a) : "l"(p));
    return a;
}
__device__ __forceinline__ float rrelu(float x) { return x >= 0.f ? x : x * SLOPE; }

// split (f0,f1) into f16x2 hi + f16x2 lo (packed b32)
__device__ __forceinline__ void cvt_hilo(float f0, float f1, uint32_t& h, uint32_t& l) {
    __half2 hh = __floats2half2_rn(f0, f1);
    float r0 = f0 - __half2float(__low2half(hh));
    float r1 = f1 - __half2float(__high2half(hh));
    __half2 ll = __floats2half2_rn(r0, r1);
    h = *reinterpret_cast<uint32_t*>(&hh);
    l = *reinterpret_cast<uint32_t*>(&ll);
}
__device__ __forceinline__ uint32_t cvt_h2(float f0, float f1) {
    __half2 hh = __floats2half2_rn(f0, f1);
    return *reinterpret_cast<uint32_t*>(&hh);
}

#define LDSM_X4(r0, r1, r2, r3, addr) \
    asm volatile("ldmatrix.sync.aligned.m8n8.x4.shared.b16 {%0,%1,%2,%3}, [%4];" \
        : "=r"(r0), "=r"(r1), "=r"(r2), "=r"(r3) : "r"(addr))
#define LDSM_X4_T(r0, r1, r2, r3, addr) \
    asm volatile("ldmatrix.sync.aligned.m8n8.x4.trans.shared.b16 {%0,%1,%2,%3}, [%4];" \
        : "=r"(r0), "=r"(r1), "=r"(r2), "=r"(r3) : "r"(addr))

__device__ __forceinline__ void mma_f16(float (&c)[4], uint32_t a0, uint32_t a1,
                                        uint32_t a2, uint32_t a3,
                                        uint32_t b0, uint32_t b1) {
    asm volatile(
        "mma.sync.aligned.m16n8k16.row.col.f32.f16.f16.f32 "
        "{%0,%1,%2,%3}, {%4,%5,%6,%7}, {%8,%9}, {%0,%1,%2,%3};"
        : "+f"(c[0]), "+f"(c[1]), "+f"(c[2]), "+f"(c[3])
        : "r"(a0), "r"(a1), "r"(a2), "r"(a3), "r"(b0), "r"(b1));
}

// ---------------------------------------------------------------------------
// fused: per (split, batch) block — 128-token tile
// GEMM [128x128]x[128x128] via mma.sync fp16 2-pass (Xhi*W + Xlo*W, fp32 acc)
// ---------------------------------------------------------------------------
__global__ void __launch_bounds__(TPB, 2)
fused_attn(const float* __restrict__ ts, const float* __restrict__ seq,
           const int* __restrict__ lengths,
           const float* __restrict__ Wk, const float* __restrict__ bk,
           const float* __restrict__ Wq, const float* __restrict__ bq,
           const float* __restrict__ Wv, const float* __restrict__ bv) {
    int b   = blockIdx.y;
    int sp  = blockIdx.x;
    int len = lengths[b];
    int start = sp * TILE_M;
    int tid = threadIdx.x;
    int wid = tid >> 5, lane = tid & 31;
    int idx = b * NSPLIT + sp;

    if (start >= len) {
        if (tid < H_) g_acc[idx * H_ + tid] = 0.f;
        if (tid == 0) { g_m[idx] = -INFINITY; g_s[idx] = 0.f; }
        return;
    }

    extern __shared__ char smem[];
    uint32_t sb = smem_u32(smem);
    float* sQ     = (float*)smem;            // 64
    float* sScore = (float*)(smem + 256);    // 128
    float* sBias  = (float*)(smem + 768);    // 128
    float* sXlast = (float*)(smem + 1280);   // 128
    float* sRed   = (float*)(smem + 1792);   // 8*64

    // ---- bias + last-token row ----
    if (tid < DIN) {
        sBias[tid] = (tid < H_) ? bk[tid] : bv[tid - H_];
        int l = len - 1;
        sXlast[tid] = (tid < DTS) ? ts[((size_t)b * L_ + l) * DTS + tid]
                                  : seq[((size_t)b * L_ + l) * DSEQ + (tid - DTS)];
    }

    // ---- X tile: fp32 -> fp16 hi/lo, swizzled [row][(ch ^ row&7)*16B] ----
#pragma unroll
    for (int it = 0; it < 8; ++it) {
        int j = tid + it * TPB;               // 0..2047
        int row = j >> 4, ch = j & 15;
        int token = start + row;
        const float* src = (ch == 0)
            ? (ts + ((size_t)b * L_ + token) * DTS)
            : (seq + ((size_t)b * L_ + token) * DSEQ + (ch * 8 - 8));
        float4 f0 = ((const float4*)src)[0];
        float4 f1 = ((const float4*)src)[1];
        uint32_t h[4], l[4];
        cvt_hilo(f0.x, f0.y, h[0], l[0]);
        cvt_hilo(f0.z, f0.w, h[1], l[1]);
        cvt_hilo(f1.x, f1.y, h[2], l[2]);
        cvt_hilo(f1.z, f1.w, h[3], l[3]);
        uint32_t off = (uint32_t)(row * 256 + ((ch ^ (row & 7)) << 4));
        *(uint4*)(smem + XH_OFF + off) = make_uint4(h[0], h[1], h[2], h[3]);
        *(uint4*)(smem + XL_OFF + off) = make_uint4(l[0], l[1], l[2], l[3]);
    }

    // ---- W tile: [Wk | Wv] fp32 -> fp16 (hi only), same swizzle ----
#pragma unroll
    for (int it = 0; it < 8; ++it) {
        int j = tid + it * TPB;               // 0..2047
        int k = j >> 4, ch = j & 15;
        int n0 = ch * 8;
        const float* src = (n0 < H_) ? (Wk + k * H_ + n0) : (Wv + k * H_ + n0 - H_);
        float4 f0 = ((const float4*)src)[0];
        float4 f1 = ((const float4*)src)[1];
        uint4 v = make_uint4(cvt_h2(f0.x, f0.y), cvt_h2(f0.z, f0.w),
                             cvt_h2(f1.x, f1.y), cvt_h2(f1.z, f1.w));
        uint32_t off = (uint32_t)(k * 256 + ((ch ^ (k & 7)) << 4));
        *(uint4*)(smem + WH_OFF + off) = v;
    }
    __syncthreads();

    // ---- q = rrelu(x_last @ Wq + bq): 4 threads per h (fp32 exact) ----
    {
        int h = tid >> 2, part = tid & 3;
        float s = 0.f;
        const float* wq = Wq + part * 32 * H_ + h;
#pragma unroll 8
        for (int d = 0; d < 32; ++d) s += sXlast[part * 32 + d] * wq[d * H_];
        s += __shfl_xor_sync(0xffffffffu, s, 1);
        s += __shfl_xor_sync(0xffffffffu, s, 2);
        if (part == 0) sQ[h] = rrelu(s + bq[h]);
    }
    __syncthreads();

    // ---- GEMM: warp owns rows [16*wid, 16*wid+16), all 128 cols ----
    float acc[16][4];
#pragma unroll
    for (int n = 0; n < 16; ++n)
#pragma unroll
        for (int i = 0; i < 4; ++i) acc[n][i] = 0.f;

    int li = lane >> 3, lr = lane & 7;
    int roff = ((li & 1) << 3) + lr;          // 0..15 row within warp tile
    int ci   = li >> 1;                       // 16B sub-chunk 0/1
    int rm   = roff & 7;                      // swizzle key
    uint32_t xh_row = sb + XH_OFF + (uint32_t)((wid * 16 + roff) * 256);
    uint32_t xl_row = xh_row + (XL_OFF - XH_OFF);

#pragma unroll
    for (int ks = 0; ks < 8; ++ks) {
        uint32_t aoff = (uint32_t)((((2 * ks + ci) ^ rm)) << 4);
        uint32_t ah0, ah1, ah2, ah3, al0, al1, al2, al3;
        LDSM_X4(ah0, ah1, ah2, ah3, xh_row + aoff);
        LDSM_X4(al0, al1, al2, al3, xl_row + aoff);
        uint32_t wh_row = sb + WH_OFF + (uint32_t)((ks * 16 + roff) * 256);
#pragma unroll
        for (int ntp = 0; ntp < 8; ++ntp) {
            uint32_t boff = (uint32_t)((((2 * ntp + ci) ^ rm)) << 4);
            uint32_t bh0, bh1, bh2, bh3;
            LDSM_X4_T(bh0, bh1, bh2, bh3, wh_row + boff);
            mma_f16(acc[2 * ntp],     ah0, ah1, ah2, ah3, bh0, bh1);
            mma_f16(acc[2 * ntp + 1], ah0, ah1, ah2, ah3, bh2, bh3);
            mma_f16(acc[2 * ntp],     al0, al1, al2, al3, bh0, bh1);
            mma_f16(acc[2 * ntp + 1], al0, al1, al2, al3, bh2, bh3);
        }
    }

    // fragment coords: lane holds rows g, g+8; cols 8*nt + 2t, +1
    int g = lane >> 2, t = lane & 3;
    int r0 = wid * 16 + g, r1 = r0 + 8;

    // ---- K epilogue: scores for this warp's 16 rows ----
    {
        float s0 = 0.f, s1 = 0.f;
#pragma unroll
        for (int nt = 0; nt < 8; ++nt) {
            int c0 = 8 * nt + 2 * t, c1 = c0 + 1;
            float q0 = sQ[c0], q1 = sQ[c1];
            float b0 = sBias[c0], b1 = sBias[c1];
            s0 += q0 * rrelu(acc[nt][0] + b0) + q1 * rrelu(acc[nt][1] + b1);
            s1 += q0 * rrelu(acc[nt][2] + b0) + q1 * rrelu(acc[nt][3] + b1);
        }
        s0 += __shfl_xor_sync(0xffffffffu, s0, 1);
        s0 += __shfl_xor_sync(0xffffffffu, s0, 2);
        s1 += __shfl_xor_sync(0xffffffffu, s1, 1);
        s1 += __shfl_xor_sync(0xffffffffu, s1, 2);
        if (t == 0) {
            sScore[r0] = (start + r0 < len) ? s0 : -INFINITY;
            sScore[r1] = (start + r1 < len) ? s1 : -INFINITY;
        }
    }
    __syncthreads();

    // ---- softmax over the 128 scores (warp 0) ----
    if (wid == 0) {
        float v0 = sScore[lane], v1 = sScore[lane + 32];
        float v2 = sScore[lane + 64], v3 = sScore[lane + 96];
        float mx = fmaxf(fmaxf(v0, v1), fmaxf(v2, v3));
#pragma unroll
        for (int o = 16; o >= 1; o >>= 1)
            mx = fmaxf(mx, __shfl_xor_sync(0xffffffffu, mx, o));
        float e0 = __expf(v0 - mx), e1 = __expf(v1 - mx);
        float e2 = __expf(v2 - mx), e3 = __expf(v3 - mx);
        float sum = e0 + e1 + e2 + e3;
#pragma unroll
        for (int o = 16; o >= 1; o >>= 1)
            sum += __shfl_xor_sync(0xffffffffu, sum, o);
        sScore[lane] = e0; sScore[lane + 32] = e1;
        sScore[lane + 64] = e2; sScore[lane + 96] = e3;
        if (lane == 0) { g_m[idx] = mx; g_s[idx] = sum; }
    }
    __syncthreads();

    // ---- V epilogue: out[c] += w[m] * rrelu(V[m][c]) ----
    {
        float w0 = sScore[r0], w1 = sScore[r1];
#pragma unroll
        for (int nt = 0; nt < 8; ++nt) {
            int c0 = 8 * nt + 2 * t, c1 = c0 + 1;   // V col (0..63)
            float b0 = sBias[64 + c0], b1 = sBias[64 + c1];
            float p0 = w0 * rrelu(acc[8 + nt][0] + b0) + w1 * rrelu(acc[8 + nt][2] + b0);
            float p1 = w0 * rrelu(acc[8 + nt][1] + b1) + w1 * rrelu(acc[8 + nt][3] + b1);
            p0 += __shfl_xor_sync(0xffffffffu, p0, 4);
            p0 += __shfl_xor_sync(0xffffffffu, p0, 8);
            p0 += __shfl_xor_sync(0xffffffffu, p0, 16);
            p1 += __shfl_xor_sync(0xffffffffu, p1, 4);
            p1 += __shfl_xor_sync(0xffffffffu, p1, 8);
            p1 += __shfl_xor_sync(0xffffffffu, p1, 16);
            if (g == 0) {
                sRed[wid * 64 + c0] = p0;
                sRed[wid * 64 + c1] = p1;
            }
        }
    }
    __syncthreads();

    if (tid < H_) {
        float a = 0.f;
#pragma unroll
        for (int w = 0; w < 8; ++w) a += sRed[w * 64 + tid];
        g_acc[idx * H_ + tid] = a;
    }
}

// ---------------------------------------------------------------------------
__global__ void combine_kernel(float* __restrict__ out) {
    int b = blockIdx.x;
    int h = threadIdx.x;
    float M = -INFINITY;
#pragma unroll
    for (int i = 0; i < NSPLIT; ++i) M = fmaxf(M, g_m[b * NSPLIT + i]);
    float S = 0.f, A = 0.f;
#pragma unroll
    for (int i = 0; i < NSPLIT; ++i) {
        float e = __expf(g_m[b * NSPLIT + i] - M);
        S += g_s[b * NSPLIT + i] * e;
        A += g_acc[(b * NSPLIT + i) * H_ + h] * e;
    }
    out[b * H_ + h] = A / S;
}

// ---------------------------------------------------------------------------
extern "C" void kernel_launch(void* const* d_in, const int* in_sizes, int n_in,
                              void* d_out, int out_size) {
    const float* ts      = (const float*)d_in[0];
    const float* seq     = (const float*)d_in[1];
    const int*   lengths = (const int*)  d_in[2];
    const float* Wk      = (const float*)d_in[3];
    const float* bk      = (const float*)d_in[4];
    const float* Wq      = (const float*)d_in[5];
    const float* bq      = (const float*)d_in[6];
    const float* Wv      = (const float*)d_in[7];
    const float* bv      = (const float*)d_in[8];
    float* out = (float*)d_out;

    static int configured = 0;
    if (!configured) {
        cudaFuncSetAttribute(fused_attn,
                             cudaFuncAttributeMaxDynamicSharedMemorySize, SMEM_TOTAL);
        configured = 1;
    }

    dim3 grid(NSPLIT, B_);
    fused_attn<<<grid, TPB, SMEM_TOTAL>>>(ts, seq, lengths, Wk, bk, Wq, bq, Wv, bv);
    combine_kernel<<<B_, H_>>>(out);
}

// round 5
// speedup vs baseline: 2.2811x; 1.0186x over previous
#include <cuda_runtime.h>
#include <cuda_fp16.h>
#include <cstdint>
#include <math.h>

#define B_      64
#define L_      2048
#define DTS     8
#define DSEQ    120
#define DIN     128
#define H_      64
#define NSPLIT  16
#define TILE_M  128
#define TPB     256
#define SLOPE   0.2291666666666667f

// smem layout (bytes): header 4KB, then XH, WH tiles (32KB each)
#define HDR     4096
#define XH_OFF  (HDR + 0)
#define WH_OFF  (HDR + 32768)
#define SMEM_TOTAL (HDR + 65536)   // 69632 B -> 2 blocks/SM (reg-limited anyway)

__device__ float g_m[B_ * NSPLIT];
__device__ float g_s[B_ * NSPLIT];
__device__ float g_acc[B_ * NSPLIT * H_];
__device__ int   g_cnt[B_];        // zero-init; self-resetting per replay

__device__ __forceinline__ uint32_t smem_u32(const void* p) {
    uint32_t a;
    asm("{ .reg .u64 t; cvta.to.shared.u64 t, %1; cvt.u32.u64 %0, t; }" : "=r"(a) : "l"(p));
    return a;
}
__device__ __forceinline__ float rrelu(float x) { return x >= 0.f ? x : x * SLOPE; }
__device__ __forceinline__ uint32_t cvt_h2(float f0, float f1) {
    __half2 hh = __floats2half2_rn(f0, f1);
    return *reinterpret_cast<uint32_t*>(&hh);
}

#define LDSM_X4(r0, r1, r2, r3, addr) \
    asm volatile("ldmatrix.sync.aligned.m8n8.x4.shared.b16 {%0,%1,%2,%3}, [%4];" \
        : "=r"(r0), "=r"(r1), "=r"(r2), "=r"(r3) : "r"(addr))
#define LDSM_X4_T(r0, r1, r2, r3, addr) \
    asm volatile("ldmatrix.sync.aligned.m8n8.x4.trans.shared.b16 {%0,%1,%2,%3}, [%4];" \
        : "=r"(r0), "=r"(r1), "=r"(r2), "=r"(r3) : "r"(addr))

__device__ __forceinline__ void mma_f16(float (&c)[4], uint32_t a0, uint32_t a1,
                                        uint32_t a2, uint32_t a3,
                                        uint32_t b0, uint32_t b1) {
    asm volatile(
        "mma.sync.aligned.m16n8k16.row.col.f32.f16.f16.f32 "
        "{%0,%1,%2,%3}, {%4,%5,%6,%7}, {%8,%9}, {%0,%1,%2,%3};"
        : "+f"(c[0]), "+f"(c[1]), "+f"(c[2]), "+f"(c[3])
        : "r"(a0), "r"(a1), "r"(a2), "r"(a3), "r"(b0), "r"(b1));
}

// ---------------------------------------------------------------------------
// fused: per (split, batch) block — 128-token tile; single fp16 pass GEMM;
// last live block per batch merges all split partials and writes out[b].
// ---------------------------------------------------------------------------
__global__ void __launch_bounds__(TPB, 2)
fused_attn(const float* __restrict__ ts, const float* __restrict__ seq,
           const int* __restrict__ lengths,
           const float* __restrict__ Wk, const float* __restrict__ bk,
           const float* __restrict__ Wq, const float* __restrict__ bq,
           const float* __restrict__ Wv, const float* __restrict__ bv,
           float* __restrict__ out) {
    int b   = blockIdx.y;
    int sp  = blockIdx.x;
    int len = lengths[b];
    int start = sp * TILE_M;
    int tid = threadIdx.x;
    int wid = tid >> 5, lane = tid & 31;
    int idx = b * NSPLIT + sp;
    int nlive = min(NSPLIT, (len + TILE_M - 1) / TILE_M);

    if (sp >= nlive) return;   // dead split: no work, no partials needed

    extern __shared__ char smem[];
    uint32_t sb = smem_u32(smem);
    float* sQ     = (float*)smem;            // 64
    float* sScore = (float*)(smem + 256);    // 128
    float* sBias  = (float*)(smem + 768);    // 128
    float* sXlast = (float*)(smem + 1280);   // 128
    float* sRed   = (float*)(smem + 1792);   // 8*64
    int*   sLast  = (int*)(smem + 4000);

    // ---- bias + last-token row ----
    if (tid < DIN) {
        sBias[tid] = (tid < H_) ? bk[tid] : bv[tid - H_];
        int l = len - 1;
        sXlast[tid] = (tid < DTS) ? ts[((size_t)b * L_ + l) * DTS + tid]
                                  : seq[((size_t)b * L_ + l) * DSEQ + (tid - DTS)];
    }

    // ---- X tile: fp32 -> fp16, swizzled [row][(ch ^ row&7)*16B] ----
#pragma unroll
    for (int it = 0; it < 8; ++it) {
        int j = tid + it * TPB;               // 0..2047
        int row = j >> 4, ch = j & 15;
        int token = start + row;
        const float* src = (ch == 0)
            ? (ts + ((size_t)b * L_ + token) * DTS)
            : (seq + ((size_t)b * L_ + token) * DSEQ + (ch * 8 - 8));
        float4 f0 = ((const float4*)src)[0];
        float4 f1 = ((const float4*)src)[1];
        uint4 v = make_uint4(cvt_h2(f0.x, f0.y), cvt_h2(f0.z, f0.w),
                             cvt_h2(f1.x, f1.y), cvt_h2(f1.z, f1.w));
        uint32_t off = (uint32_t)(row * 256 + ((ch ^ (row & 7)) << 4));
        *(uint4*)(smem + XH_OFF + off) = v;
    }

    // ---- W tile: [Wk | Wv] fp32 -> fp16, same swizzle ----
#pragma unroll
    for (int it = 0; it < 8; ++it) {
        int j = tid + it * TPB;               // 0..2047
        int k = j >> 4, ch = j & 15;
        int n0 = ch * 8;
        const float* src = (n0 < H_) ? (Wk + k * H_ + n0) : (Wv + k * H_ + n0 - H_);
        float4 f0 = ((const float4*)src)[0];
        float4 f1 = ((const float4*)src)[1];
        uint4 v = make_uint4(cvt_h2(f0.x, f0.y), cvt_h2(f0.z, f0.w),
                             cvt_h2(f1.x, f1.y), cvt_h2(f1.z, f1.w));
        uint32_t off = (uint32_t)(k * 256 + ((ch ^ (k & 7)) << 4));
        *(uint4*)(smem + WH_OFF + off) = v;
    }
    __syncthreads();

    // ---- q = rrelu(x_last @ Wq + bq): 4 threads per h (fp32 exact) ----
    {
        int h = tid >> 2, part = tid & 3;
        float s = 0.f;
        const float* wq = Wq + part * 32 * H_ + h;
#pragma unroll 8
        for (int d = 0; d < 32; ++d) s += sXlast[part * 32 + d] * wq[d * H_];
        s += __shfl_xor_sync(0xffffffffu, s, 1);
        s += __shfl_xor_sync(0xffffffffu, s, 2);
        if (part == 0) sQ[h] = rrelu(s + bq[h]);
    }
    __syncthreads();

    // ---- GEMM: warp owns rows [16*wid, 16*wid+16), all 128 cols ----
    float acc[16][4];
#pragma unroll
    for (int n = 0; n < 16; ++n)
#pragma unroll
        for (int i = 0; i < 4; ++i) acc[n][i] = 0.f;

    int li = lane >> 3, lr = lane & 7;
    int roff = ((li & 1) << 3) + lr;          // 0..15 row within warp tile
    int ci   = li >> 1;                       // 16B sub-chunk 0/1
    int rm   = roff & 7;                      // swizzle key
    uint32_t xh_row = sb + XH_OFF + (uint32_t)((wid * 16 + roff) * 256);

#pragma unroll
    for (int ks = 0; ks < 8; ++ks) {
        uint32_t aoff = (uint32_t)((((2 * ks + ci) ^ rm)) << 4);
        uint32_t ah0, ah1, ah2, ah3;
        LDSM_X4(ah0, ah1, ah2, ah3, xh_row + aoff);
        uint32_t wh_row = sb + WH_OFF + (uint32_t)((ks * 16 + roff) * 256);
#pragma unroll
        for (int ntp = 0; ntp < 8; ++ntp) {
            uint32_t boff = (uint32_t)((((2 * ntp + ci) ^ rm)) << 4);
            uint32_t bh0, bh1, bh2, bh3;
            LDSM_X4_T(bh0, bh1, bh2, bh3, wh_row + boff);
            mma_f16(acc[2 * ntp],     ah0, ah1, ah2, ah3, bh0, bh1);
            mma_f16(acc[2 * ntp + 1], ah0, ah1, ah2, ah3, bh2, bh3);
        }
    }

    // fragment coords: lane holds rows g, g+8; cols 8*nt + 2t, +1
    int g = lane >> 2, t = lane & 3;
    int r0 = wid * 16 + g, r1 = r0 + 8;

    // ---- K epilogue: scores for this warp's 16 rows ----
    {
        float s0 = 0.f, s1 = 0.f;
#pragma unroll
        for (int nt = 0; nt < 8; ++nt) {
            int c0 = 8 * nt + 2 * t, c1 = c0 + 1;
            float q0 = sQ[c0], q1 = sQ[c1];
            float b0 = sBias[c0], b1 = sBias[c1];
            s0 += q0 * rrelu(acc[nt][0] + b0) + q1 * rrelu(acc[nt][1] + b1);
            s1 += q0 * rrelu(acc[nt][2] + b0) + q1 * rrelu(acc[nt][3] + b1);
        }
        s0 += __shfl_xor_sync(0xffffffffu, s0, 1);
        s0 += __shfl_xor_sync(0xffffffffu, s0, 2);
        s1 += __shfl_xor_sync(0xffffffffu, s1, 1);
        s1 += __shfl_xor_sync(0xffffffffu, s1, 2);
        if (t == 0) {
            sScore[r0] = (start + r0 < len) ? s0 : -INFINITY;
            sScore[r1] = (start + r1 < len) ? s1 : -INFINITY;
        }
    }
    __syncthreads();

    // ---- softmax over the 128 scores (warp 0) ----
    if (wid == 0) {
        float v0 = sScore[lane], v1 = sScore[lane + 32];
        float v2 = sScore[lane + 64], v3 = sScore[lane + 96];
        float mx = fmaxf(fmaxf(v0, v1), fmaxf(v2, v3));
#pragma unroll
        for (int o = 16; o >= 1; o >>= 1)
            mx = fmaxf(mx, __shfl_xor_sync(0xffffffffu, mx, o));
        float e0 = __expf(v0 - mx), e1 = __expf(v1 - mx);
        float e2 = __expf(v2 - mx), e3 = __expf(v3 - mx);
        float sum = e0 + e1 + e2 + e3;
#pragma unroll
        for (int o = 16; o >= 1; o >>= 1)
            sum += __shfl_xor_sync(0xffffffffu, sum, o);
        sScore[lane] = e0; sScore[lane + 32] = e1;
        sScore[lane + 64] = e2; sScore[lane + 96] = e3;
        if (lane == 0) { g_m[idx] = mx; g_s[idx] = sum; }
    }
    __syncthreads();

    // ---- V epilogue: out[c] += w[m] * rrelu(V[m][c]) ----
    {
        float w0 = sScore[r0], w1 = sScore[r1];
#pragma unroll
        for (int nt = 0; nt < 8; ++nt) {
            int c0 = 8 * nt + 2 * t, c1 = c0 + 1;   // V col (0..63)
            float b0 = sBias[64 + c0], b1 = sBias[64 + c1];
            float p0 = w0 * rrelu(acc[8 + nt][0] + b0) + w1 * rrelu(acc[8 + nt][2] + b0);
            float p1 = w0 * rrelu(acc[8 + nt][1] + b1) + w1 * rrelu(acc[8 + nt][3] + b1);
            p0 += __shfl_xor_sync(0xffffffffu, p0, 4);
            p0 += __shfl_xor_sync(0xffffffffu, p0, 8);
            p0 += __shfl_xor_sync(0xffffffffu, p0, 16);
            p1 += __shfl_xor_sync(0xffffffffu, p1, 4);
            p1 += __shfl_xor_sync(0xffffffffu, p1, 8);
            p1 += __shfl_xor_sync(0xffffffffu, p1, 16);
            if (g == 0) {
                sRed[wid * 64 + c0] = p0;
                sRed[wid * 64 + c1] = p1;
            }
        }
    }
    __syncthreads();

    if (tid < H_) {
        float a = 0.f;
#pragma unroll
        for (int w = 0; w < 8; ++w) a += sRed[w * 64 + tid];
        g_acc[idx * H_ + tid] = a;
    }

    // ---- last-block combine (threadfence reduction) ----
    __threadfence();
    __syncthreads();
    if (tid == 0) {
        int old = atomicAdd(&g_cnt[b], 1);
        *sLast = (old == nlive - 1);
    }
    __syncthreads();
    if (*sLast) {
        if (tid < H_) {
            volatile float* vm = g_m + b * NSPLIT;
            volatile float* vs = g_s + b * NSPLIT;
            volatile float* va = g_acc + (size_t)b * NSPLIT * H_;
            float M = -INFINITY;
            for (int i = 0; i < nlive; ++i) M = fmaxf(M, vm[i]);
            float S = 0.f, A = 0.f;
            for (int i = 0; i < nlive; ++i) {
                float e = __expf(vm[i] - M);
                S += vs[i] * e;
                A += va[i * H_ + tid] * e;
            }
            out[b * H_ + tid] = A / S;
        }
        if (tid == 0) g_cnt[b] = 0;   // reset for next replay
    }
}

// ---------------------------------------------------------------------------
extern "C" void kernel_launch(void* const* d_in, const int* in_sizes, int n_in,
                              void* d_out, int out_size) {
    const float* ts      = (const float*)d_in[0];
    const float* seq     = (const float*)d_in[1];
    const int*   lengths = (const int*)  d_in[2];
    const float* Wk      = (const float*)d_in[3];
    const float* bk      = (const float*)d_in[4];
    const float* Wq      = (const float*)d_in[5];
    const float* bq      = (const float*)d_in[6];
    const float* Wv      = (const float*)d_in[7];
    const float* bv      = (const float*)d_in[8];
    float* out = (float*)d_out;

    static int configured = 0;
    if (!configured) {
        cudaFuncSetAttribute(fused_attn,
                             cudaFuncAttributeMaxDynamicSharedMemorySize, SMEM_TOTAL);
        configured = 1;
    }

    dim3 grid(NSPLIT, B_);
    fused_attn<<<grid, TPB, SMEM_TOTAL>>>(ts, seq, lengths, Wk, bk, Wq, bq, Wv, bv, out);
}

// round 6
// speedup vs baseline: 2.5315x; 1.1098x over previous
#include <cuda_runtime.h>
#include <cuda_fp16.h>
#include <cstdint>
#include <math.h>

#define B_      64
#define L_      2048
#define DTS     8
#define DSEQ    120
#define DIN     128
#define H_      64
#define NSPLIT  16
#define TILE_M  128
#define TPB     256
#define SLOPE   0.2291666666666667f

// smem layout (bytes): header 4KB, then XH, WH tiles (32KB each)
#define HDR     4096
#define XH_OFF  (HDR + 0)
#define WH_OFF  (HDR + 32768)
#define SMEM_TOTAL (HDR + 65536)

__device__ float g_m[B_ * NSPLIT];
__device__ float g_s[B_ * NSPLIT];
__device__ float g_acc[B_ * NSPLIT * H_];
__device__ int   g_cnt[B_];        // zero-init; self-resetting per replay

__device__ __forceinline__ uint32_t smem_u32(const void* p) {
    uint32_t a;
    asm("{ .reg .u64 t; cvta.to.shared.u64 t, %1; cvt.u32.u64 %0, t; }" : "=r"(a) : "l"(p));
    return a;
}
__device__ __forceinline__ float rrelu(float x) { return x >= 0.f ? x : x * SLOPE; }
__device__ __forceinline__ uint32_t cvt_h2(float f0, float f1) {
    __half2 hh = __floats2half2_rn(f0, f1);
    return *reinterpret_cast<uint32_t*>(&hh);
}

#define LDSM_X4(r0, r1, r2, r3, addr) \
    asm volatile("ldmatrix.sync.aligned.m8n8.x4.shared.b16 {%0,%1,%2,%3}, [%4];" \
        : "=r"(r0), "=r"(r1), "=r"(r2), "=r"(r3) : "r"(addr))
#define LDSM_X4_T(r0, r1, r2, r3, addr) \
    asm volatile("ldmatrix.sync.aligned.m8n8.x4.trans.shared.b16 {%0,%1,%2,%3}, [%4];" \
        : "=r"(r0), "=r"(r1), "=r"(r2), "=r"(r3) : "r"(addr))

__device__ __forceinline__ void mma_f16(float (&c)[4], uint32_t a0, uint32_t a1,
                                        uint32_t a2, uint32_t a3,
                                        uint32_t b0, uint32_t b1) {
    asm volatile(
        "mma.sync.aligned.m16n8k16.row.col.f32.f16.f16.f32 "
        "{%0,%1,%2,%3}, {%4,%5,%6,%7}, {%8,%9}, {%0,%1,%2,%3};"
        : "+f"(c[0]), "+f"(c[1]), "+f"(c[2]), "+f"(c[3])
        : "r"(a0), "r"(a1), "r"(a2), "r"(a3), "r"(b0), "r"(b1));
}

// ---------------------------------------------------------------------------
// fused: per (split, batch) block — 128-token tile.
// Warp specialization: warps 0-3 compute K = X@Wk (cols 0-63), each 32 rows;
// warps 4-7 compute V = X@Wv (cols 64-127), each 32 rows.
// ---------------------------------------------------------------------------
__global__ void __launch_bounds__(TPB, 2)
fused_attn(const float* __restrict__ ts, const float* __restrict__ seq,
           const int* __restrict__ lengths,
           const float* __restrict__ Wk, const float* __restrict__ bk,
           const float* __restrict__ Wq, const float* __restrict__ bq,
           const float* __restrict__ Wv, const float* __restrict__ bv,
           float* __restrict__ out) {
    int b   = blockIdx.y;
    int sp  = blockIdx.x;
    int len = lengths[b];
    int start = sp * TILE_M;
    int tid = threadIdx.x;
    int wid = tid >> 5, lane = tid & 31;
    int idx = b * NSPLIT + sp;
    int nlive = min(NSPLIT, (len + TILE_M - 1) / TILE_M);

    if (sp >= nlive) return;   // dead split

    extern __shared__ char smem[];
    uint32_t sb = smem_u32(smem);
    float* sQ     = (float*)smem;            // 64
    float* sScore = (float*)(smem + 256);    // 128
    float* sBias  = (float*)(smem + 768);    // 128
    float* sXlast = (float*)(smem + 1280);   // 128
    float* sRed   = (float*)(smem + 1792);   // 4*64 (q partials, then V partials)
    int*   sLast  = (int*)(smem + 4000);

    // ---- bias + last-token row ----
    if (tid < DIN) {
        sBias[tid] = (tid < H_) ? bk[tid] : bv[tid - H_];
        int l = len - 1;
        sXlast[tid] = (tid < DTS) ? ts[((size_t)b * L_ + l) * DTS + tid]
                                  : seq[((size_t)b * L_ + l) * DSEQ + (tid - DTS)];
    }

    // ---- X tile: fp32 -> fp16, swizzled [row][(ch ^ row&7)*16B] ----
#pragma unroll
    for (int it = 0; it < 8; ++it) {
        int j = tid + it * TPB;               // 0..2047
        int row = j >> 4, ch = j & 15;
        int token = start + row;
        const float* src = (ch == 0)
            ? (ts + ((size_t)b * L_ + token) * DTS)
            : (seq + ((size_t)b * L_ + token) * DSEQ + (ch * 8 - 8));
        float4 f0 = ((const float4*)src)[0];
        float4 f1 = ((const float4*)src)[1];
        uint4 v = make_uint4(cvt_h2(f0.x, f0.y), cvt_h2(f0.z, f0.w),
                             cvt_h2(f1.x, f1.y), cvt_h2(f1.z, f1.w));
        uint32_t off = (uint32_t)(row * 256 + ((ch ^ (row & 7)) << 4));
        *(uint4*)(smem + XH_OFF + off) = v;
    }

    // ---- W tile: [Wk | Wv] fp32 -> fp16, same swizzle ----
#pragma unroll
    for (int it = 0; it < 8; ++it) {
        int j = tid + it * TPB;               // 0..2047
        int k = j >> 4, ch = j & 15;
        int n0 = ch * 8;
        const float* src = (n0 < H_) ? (Wk + k * H_ + n0) : (Wv + k * H_ + n0 - H_);
        float4 f0 = ((const float4*)src)[0];
        float4 f1 = ((const float4*)src)[1];
        uint4 v = make_uint4(cvt_h2(f0.x, f0.y), cvt_h2(f0.z, f0.w),
                             cvt_h2(f1.x, f1.y), cvt_h2(f1.z, f1.w));
        uint32_t off = (uint32_t)(k * 256 + ((ch ^ (k & 7)) << 4));
        *(uint4*)(smem + WH_OFF + off) = v;
    }
    __syncthreads();

    // ---- q partials: coalesced (h = tid&63, part = tid>>6) ----
    {
        int h = tid & 63, part = tid >> 6;
        float s = 0.f;
        const float* wq = Wq + part * 32 * H_ + h;
#pragma unroll 8
        for (int d = 0; d < 32; ++d) s += sXlast[part * 32 + d] * wq[d * H_];
        sRed[part * 64 + h] = s;
    }
    __syncthreads();
    if (tid < H_) {
        float s = sRed[tid] + sRed[64 + tid] + sRed[128 + tid] + sRed[192 + tid];
        sQ[tid] = rrelu(s + bq[tid]);
    }
    __syncthreads();

    // ---- GEMM: warp (wid&3) owns rows [32*(wid&3), +32); K/V half by wid>=4 ----
    float acc[2][8][4];
#pragma unroll
    for (int ms = 0; ms < 2; ++ms)
#pragma unroll
        for (int n = 0; n < 8; ++n)
#pragma unroll
            for (int i = 0; i < 4; ++i) acc[ms][n][i] = 0.f;

    int kw = wid & 3;
    int isV = wid >> 2;                       // 0 = K half, 1 = V half
    uint32_t nchunk = (uint32_t)(isV << 3);   // col-chunk base: 0 or 8

    int li = lane >> 3, lr = lane & 7;
    int roff = ((li & 1) << 3) + lr;          // 0..15 row within 16-row subtile
    int ci   = li >> 1;                       // 16B sub-chunk 0/1
    int rm   = roff & 7;                      // swizzle key
    uint32_t a_row0 = sb + XH_OFF + (uint32_t)((kw * 32 + roff) * 256);
    uint32_t a_row1 = a_row0 + 16 * 256;

#pragma unroll
    for (int ks = 0; ks < 8; ++ks) {
        uint32_t aoff = (uint32_t)((((2 * ks + ci) ^ rm)) << 4);
        uint32_t a00, a01, a02, a03, a10, a11, a12, a13;
        LDSM_X4(a00, a01, a02, a03, a_row0 + aoff);
        LDSM_X4(a10, a11, a12, a13, a_row1 + aoff);
        uint32_t wh_row = sb + WH_OFF + (uint32_t)((ks * 16 + roff) * 256);
#pragma unroll
        for (int ntp = 0; ntp < 4; ++ntp) {
            uint32_t boff = (uint32_t)(((nchunk + 2 * ntp + ci) ^ rm) << 4);
            uint32_t b0, b1, b2, b3;
            LDSM_X4_T(b0, b1, b2, b3, wh_row + boff);
            mma_f16(acc[0][2 * ntp],     a00, a01, a02, a03, b0, b1);
            mma_f16(acc[0][2 * ntp + 1], a00, a01, a02, a03, b2, b3);
            mma_f16(acc[1][2 * ntp],     a10, a11, a12, a13, b0, b1);
            mma_f16(acc[1][2 * ntp + 1], a10, a11, a12, a13, b2, b3);
        }
    }

    // fragment coords: lane holds rows g, g+8 (per ms); cols 8*nt + 2t, +1
    int g = lane >> 2, t = lane & 3;

    // ---- K warps: scores for their 32 rows (full 64-col dot, quad-reduce) ----
    if (!isV) {
#pragma unroll
        for (int ms = 0; ms < 2; ++ms) {
            float s0 = 0.f, s1 = 0.f;
#pragma unroll
            for (int nt = 0; nt < 8; ++nt) {
                int c0 = 8 * nt + 2 * t, c1 = c0 + 1;
                float q0 = sQ[c0], q1 = sQ[c1];
                float b0 = sBias[c0], b1 = sBias[c1];
                s0 += q0 * rrelu(acc[ms][nt][0] + b0) + q1 * rrelu(acc[ms][nt][1] + b1);
                s1 += q0 * rrelu(acc[ms][nt][2] + b0) + q1 * rrelu(acc[ms][nt][3] + b1);
            }
            s0 += __shfl_xor_sync(0xffffffffu, s0, 1);
            s0 += __shfl_xor_sync(0xffffffffu, s0, 2);
            s1 += __shfl_xor_sync(0xffffffffu, s1, 1);
            s1 += __shfl_xor_sync(0xffffffffu, s1, 2);
            if (t == 0) {
                int r0 = kw * 32 + ms * 16 + g, r1 = r0 + 8;
                sScore[r0] = (start + r0 < len) ? s0 : -INFINITY;
                sScore[r1] = (start + r1 < len) ? s1 : -INFINITY;
            }
        }
    }
    __syncthreads();

    // ---- softmax over the 128 scores (warp 0) ----
    if (wid == 0) {
        float v0 = sScore[lane], v1 = sScore[lane + 32];
        float v2 = sScore[lane + 64], v3 = sScore[lane + 96];
        float mx = fmaxf(fmaxf(v0, v1), fmaxf(v2, v3));
#pragma unroll
        for (int o = 16; o >= 1; o >>= 1)
            mx = fmaxf(mx, __shfl_xor_sync(0xffffffffu, mx, o));
        float e0 = __expf(v0 - mx), e1 = __expf(v1 - mx);
        float e2 = __expf(v2 - mx), e3 = __expf(v3 - mx);
        float sum = e0 + e1 + e2 + e3;
#pragma unroll
        for (int o = 16; o >= 1; o >>= 1)
            sum += __shfl_xor_sync(0xffffffffu, sum, o);
        sScore[lane] = e0; sScore[lane + 32] = e1;
        sScore[lane + 64] = e2; sScore[lane + 96] = e3;
        if (lane == 0) { g_m[idx] = mx; g_s[idx] = sum; }
    }
    __syncthreads();

    // ---- V warps: weighted accumulate over their 32 rows ----
    if (isV) {
        int rbase = kw * 32;
        float wa = sScore[rbase + g];
        float wb = sScore[rbase + g + 8];
        float wc = sScore[rbase + g + 16];
        float wd = sScore[rbase + g + 24];
#pragma unroll
        for (int nt = 0; nt < 8; ++nt) {
            int c0 = 8 * nt + 2 * t, c1 = c0 + 1;   // V col (0..63)
            float b0 = sBias[64 + c0], b1 = sBias[64 + c1];
            float p0 = wa * rrelu(acc[0][nt][0] + b0) + wb * rrelu(acc[0][nt][2] + b0)
                     + wc * rrelu(acc[1][nt][0] + b0) + wd * rrelu(acc[1][nt][2] + b0);
            float p1 = wa * rrelu(acc[0][nt][1] + b1) + wb * rrelu(acc[0][nt][3] + b1)
                     + wc * rrelu(acc[1][nt][1] + b1) + wd * rrelu(acc[1][nt][3] + b1);
            p0 += __shfl_xor_sync(0xffffffffu, p0, 4);
            p0 += __shfl_xor_sync(0xffffffffu, p0, 8);
            p0 += __shfl_xor_sync(0xffffffffu, p0, 16);
            p1 += __shfl_xor_sync(0xffffffffu, p1, 4);
            p1 += __shfl_xor_sync(0xffffffffu, p1, 8);
            p1 += __shfl_xor_sync(0xffffffffu, p1, 16);
            if (g == 0) {
                sRed[kw * 64 + c0] = p0;
                sRed[kw * 64 + c1] = p1;
            }
        }
    }
    __syncthreads();

    if (tid < H_) {
        g_acc[idx * H_ + tid] = sRed[tid] + sRed[64 + tid]
                              + sRed[128 + tid] + sRed[192 + tid];
    }

    // ---- last-block combine (threadfence reduction) ----
    __threadfence();
    __syncthreads();
    if (tid == 0) {
        int old = atomicAdd(&g_cnt[b], 1);
        *sLast = (old == nlive - 1);
    }
    __syncthreads();
    if (*sLast) {
        if (tid < H_) {
            volatile float* vm = g_m + b * NSPLIT;
            volatile float* vs = g_s + b * NSPLIT;
            volatile float* va = g_acc + (size_t)b * NSPLIT * H_;
            float M = -INFINITY;
            for (int i = 0; i < nlive; ++i) M = fmaxf(M, vm[i]);
            float S = 0.f, A = 0.f;
            for (int i = 0; i < nlive; ++i) {
                float e = __expf(vm[i] - M);
                S += vs[i] * e;
                A += va[i * H_ + tid] * e;
            }
            out[b * H_ + tid] = A / S;
        }
        if (tid == 0) g_cnt[b] = 0;   // reset for next replay
    }
}

// ---------------------------------------------------------------------------
extern "C" void kernel_launch(void* const* d_in, const int* in_sizes, int n_in,
                              void* d_out, int out_size) {
    const float* ts      = (const float*)d_in[0];
    const float* seq     = (const float*)d_in[1];
    const int*   lengths = (const int*)  d_in[2];
    const float* Wk      = (const float*)d_in[3];
    const float* bk      = (const float*)d_in[4];
    const float* Wq      = (const float*)d_in[5];
    const float* bq      = (const float*)d_in[6];
    const float* Wv      = (const float*)d_in[7];
    const float* bv      = (const float*)d_in[8];
    float* out = (float*)d_out;

    static int configured = 0;
    if (!configured) {
        cudaFuncSetAttribute(fused_attn,
                             cudaFuncAttributeMaxDynamicSharedMemorySize, SMEM_TOTAL);
        configured = 1;
    }

    dim3 grid(NSPLIT, B_);
    fused_attn<<<grid, TPB, SMEM_TOTAL>>>(ts, seq, lengths, Wk, bk, Wq, bq, Wv, bv, out);
}

// round 7
// speedup vs baseline: 2.7240x; 1.0760x over previous
#include <cuda_runtime.h>
#include <cuda_fp16.h>
#include <cstdint>
#include <math.h>

#define B_      64
#define L_      2048
#define DTS     8
#define DSEQ    120
#define DIN     128
#define H_      64
#define NSPLIT  8
#define TILE_B  256              // tokens per block
#define TILE_M  128              // tokens per MMA tile
#define TPB     256
#define SLOPE   0.2291666666666667f

// smem layout (bytes): header 4KB, X0 (32KB), X1 (32KB), W (32KB)
#define HDR     4096
#define X0_OFF  4096
#define X1_OFF  36864
#define WH_OFF  69632
#define SMEM_TOTAL 102400        // 2 blocks/SM

__device__ float g_m[B_ * NSPLIT];
__device__ float g_s[B_ * NSPLIT];
__device__ float g_acc[B_ * NSPLIT * H_];
__device__ int   g_cnt[B_];      // zero-init; self-resetting per replay

__device__ __forceinline__ uint32_t smem_u32(const void* p) {
    uint32_t a;
    asm("{ .reg .u64 t; cvta.to.shared.u64 t, %1; cvt.u32.u64 %0, t; }" : "=r"(a) : "l"(p));
    return a;
}
__device__ __forceinline__ float rrelu(float x) { return x >= 0.f ? x : x * SLOPE; }
__device__ __forceinline__ uint32_t cvt_h2(float f0, float f1) {
    __half2 hh = __floats2half2_rn(f0, f1);
    return *reinterpret_cast<uint32_t*>(&hh);
}

#define LDSM_X4(r0, r1, r2, r3, addr) \
    asm volatile("ldmatrix.sync.aligned.m8n8.x4.shared.b16 {%0,%1,%2,%3}, [%4];" \
        : "=r"(r0), "=r"(r1), "=r"(r2), "=r"(r3) : "r"(addr))
#define LDSM_X4_T(r0, r1, r2, r3, addr) \
    asm volatile("ldmatrix.sync.aligned.m8n8.x4.trans.shared.b16 {%0,%1,%2,%3}, [%4];" \
        : "=r"(r0), "=r"(r1), "=r"(r2), "=r"(r3) : "r"(addr))

__device__ __forceinline__ void mma_f16(float (&c)[4], uint32_t a0, uint32_t a1,
                                        uint32_t a2, uint32_t a3,
                                        uint32_t b0, uint32_t b1) {
    asm volatile(
        "mma.sync.aligned.m16n8k16.row.col.f32.f16.f16.f32 "
        "{%0,%1,%2,%3}, {%4,%5,%6,%7}, {%8,%9}, {%0,%1,%2,%3};"
        : "+f"(c[0]), "+f"(c[1]), "+f"(c[2]), "+f"(c[3])
        : "r"(a0), "r"(a1), "r"(a2), "r"(a3), "r"(b0), "r"(b1));
}

// ---------------------------------------------------------------------------
// fused: per (split, batch) block — 256-token span, two 128-row MMA tiles.
// Warp specialization per tile: warps 0-3 K (cols 0-63), warps 4-7 V.
// ---------------------------------------------------------------------------
__global__ void __launch_bounds__(TPB, 2)
fused_attn(const float* __restrict__ ts, const float* __restrict__ seq,
           const int* __restrict__ lengths,
           const float* __restrict__ Wk, const float* __restrict__ bk,
           const float* __restrict__ Wq, const float* __restrict__ bq,
           const float* __restrict__ Wv, const float* __restrict__ bv,
           float* __restrict__ out) {
    int b   = blockIdx.y;
    int sp  = blockIdx.x;
    int len = lengths[b];
    int start = sp * TILE_B;
    int tid = threadIdx.x;
    int wid = tid >> 5, lane = tid & 31;
    int idx = b * NSPLIT + sp;
    int nlive = min(NSPLIT, (len + TILE_B - 1) / TILE_B);

    if (sp >= nlive) return;   // dead split
    int ntiles = min(2, (len - start + TILE_M - 1) >> 7);

    extern __shared__ char smem[];
    uint32_t sb = smem_u32(smem);
    float* sQ     = (float*)smem;            // 64 floats
    float* sScore = (float*)(smem + 256);    // 128 floats
    float* sBias  = (float*)(smem + 768);    // 128 floats
    float* sXlast = (float*)(smem + 1280);   // 128 floats
    float* sRed0  = (float*)(smem + 1792);   // 256 floats (also q partials)
    float* sRed1  = (float*)(smem + 2816);   // 256 floats
    int*   sLast  = (int*)(smem + 3840);

    // ---- bias + last-token row ----
    if (tid < DIN) {
        sBias[tid] = (tid < H_) ? bk[tid] : bv[tid - H_];
        int l = len - 1;
        sXlast[tid] = (tid < DTS) ? ts[((size_t)b * L_ + l) * DTS + tid]
                                  : seq[((size_t)b * L_ + l) * DSEQ + (tid - DTS)];
    }

    // ---- W tile: [Wk | Wv] fp32 -> fp16, swizzled ----
#pragma unroll
    for (int it = 0; it < 8; ++it) {
        int j = tid + it * TPB;               // 0..2047
        int k = j >> 4, ch = j & 15;
        int n0 = ch * 8;
        const float* src = (n0 < H_) ? (Wk + k * H_ + n0) : (Wv + k * H_ + n0 - H_);
        float4 f0 = ((const float4*)src)[0];
        float4 f1 = ((const float4*)src)[1];
        uint4 v = make_uint4(cvt_h2(f0.x, f0.y), cvt_h2(f0.z, f0.w),
                             cvt_h2(f1.x, f1.y), cvt_h2(f1.z, f1.w));
        uint32_t off = (uint32_t)(k * 256 + ((ch ^ (k & 7)) << 4));
        *(uint4*)(smem + WH_OFF + off) = v;
    }

    // ---- X tiles (front-batched): fp32 -> fp16, swizzled ----
    for (int tl = 0; tl < ntiles; ++tl) {
        int xoff = X0_OFF + tl * 32768;
        int tbase = start + tl * TILE_M;
#pragma unroll
        for (int it = 0; it < 8; ++it) {
            int j = tid + it * TPB;           // 0..2047
            int row = j >> 4, ch = j & 15;
            int token = tbase + row;
            const float* src = (ch == 0)
                ? (ts + ((size_t)b * L_ + token) * DTS)
                : (seq + ((size_t)b * L_ + token) * DSEQ + (ch * 8 - 8));
            float4 f0 = ((const float4*)src)[0];
            float4 f1 = ((const float4*)src)[1];
            uint4 v = make_uint4(cvt_h2(f0.x, f0.y), cvt_h2(f0.z, f0.w),
                                 cvt_h2(f1.x, f1.y), cvt_h2(f1.z, f1.w));
            uint32_t off = (uint32_t)(row * 256 + ((ch ^ (row & 7)) << 4));
            *(uint4*)(smem + xoff + off) = v;
        }
    }
    __syncthreads();

    // ---- q partials (coalesced) + finalize ----
    {
        int h = tid & 63, part = tid >> 6;
        float s = 0.f;
        const float* wq = Wq + part * 32 * H_ + h;
#pragma unroll 8
        for (int d = 0; d < 32; ++d) s += sXlast[part * 32 + d] * wq[d * H_];
        sRed0[part * 64 + h] = s;
    }
    __syncthreads();
    if (tid < H_) {
        float s = sRed0[tid] + sRed0[64 + tid] + sRed0[128 + tid] + sRed0[192 + tid];
        sQ[tid] = rrelu(s + bq[tid]);
    }
    __syncthreads();

    int kw = wid & 3;
    int isV = wid >> 2;
    uint32_t nchunk = (uint32_t)(isV << 3);

    int li = lane >> 3, lr = lane & 7;
    int roff = ((li & 1) << 3) + lr;
    int ci   = li >> 1;
    int rm   = roff & 7;
    int g = lane >> 2, t = lane & 3;

    float tm[2], tsum[2];
    tm[1] = -INFINITY; tsum[1] = 0.f;

    for (int tl = 0; tl < ntiles; ++tl) {
        int tbase = start + tl * TILE_M;
        uint32_t a_row0 = sb + X0_OFF + (uint32_t)(tl * 32768)
                        + (uint32_t)((kw * 32 + roff) * 256);
        uint32_t a_row1 = a_row0 + 16 * 256;

        // ---- GEMM ----
        float acc[2][8][4];
#pragma unroll
        for (int ms = 0; ms < 2; ++ms)
#pragma unroll
            for (int n = 0; n < 8; ++n)
#pragma unroll
                for (int i = 0; i < 4; ++i) acc[ms][n][i] = 0.f;

#pragma unroll
        for (int ks = 0; ks < 8; ++ks) {
            uint32_t aoff = (uint32_t)((((2 * ks + ci) ^ rm)) << 4);
            uint32_t a00, a01, a02, a03, a10, a11, a12, a13;
            LDSM_X4(a00, a01, a02, a03, a_row0 + aoff);
            LDSM_X4(a10, a11, a12, a13, a_row1 + aoff);
            uint32_t wh_row = sb + WH_OFF + (uint32_t)((ks * 16 + roff) * 256);
#pragma unroll
            for (int ntp = 0; ntp < 4; ++ntp) {
                uint32_t boff = (uint32_t)(((nchunk + 2 * ntp + ci) ^ rm) << 4);
                uint32_t b0, b1, b2, b3;
                LDSM_X4_T(b0, b1, b2, b3, wh_row + boff);
                mma_f16(acc[0][2 * ntp],     a00, a01, a02, a03, b0, b1);
                mma_f16(acc[0][2 * ntp + 1], a00, a01, a02, a03, b2, b3);
                mma_f16(acc[1][2 * ntp],     a10, a11, a12, a13, b0, b1);
                mma_f16(acc[1][2 * ntp + 1], a10, a11, a12, a13, b2, b3);
            }
        }

        // ---- K warps: scores ----
        if (!isV) {
#pragma unroll
            for (int ms = 0; ms < 2; ++ms) {
                float s0 = 0.f, s1 = 0.f;
#pragma unroll
                for (int nt = 0; nt < 8; ++nt) {
                    int c0 = 8 * nt + 2 * t, c1 = c0 + 1;
                    float q0 = sQ[c0], q1 = sQ[c1];
                    float b0 = sBias[c0], b1 = sBias[c1];
                    s0 += q0 * rrelu(acc[ms][nt][0] + b0) + q1 * rrelu(acc[ms][nt][1] + b1);
                    s1 += q0 * rrelu(acc[ms][nt][2] + b0) + q1 * rrelu(acc[ms][nt][3] + b1);
                }
                s0 += __shfl_xor_sync(0xffffffffu, s0, 1);
                s0 += __shfl_xor_sync(0xffffffffu, s0, 2);
                s1 += __shfl_xor_sync(0xffffffffu, s1, 1);
                s1 += __shfl_xor_sync(0xffffffffu, s1, 2);
                if (t == 0) {
                    int r0 = kw * 32 + ms * 16 + g, r1 = r0 + 8;
                    sScore[r0] = (tbase + r0 < len) ? s0 : -INFINITY;
                    sScore[r1] = (tbase + r1 < len) ? s1 : -INFINITY;
                }
            }
        }
        __syncthreads();

        // ---- all-warp redundant softmax reduction ----
        {
            float v0 = sScore[lane], v1 = sScore[lane + 32];
            float v2 = sScore[lane + 64], v3 = sScore[lane + 96];
            float mx = fmaxf(fmaxf(v0, v1), fmaxf(v2, v3));
#pragma unroll
            for (int o = 16; o >= 1; o >>= 1)
                mx = fmaxf(mx, __shfl_xor_sync(0xffffffffu, mx, o));
            float sum = __expf(v0 - mx) + __expf(v1 - mx)
                      + __expf(v2 - mx) + __expf(v3 - mx);
#pragma unroll
            for (int o = 16; o >= 1; o >>= 1)
                sum += __shfl_xor_sync(0xffffffffu, sum, o);
            tm[tl] = mx; tsum[tl] = sum;
        }

        // ---- V warps: weighted accumulate, write sRed[tl] ----
        if (isV) {
            float mx = tm[tl];
            int rbase = kw * 32;
            float wa = __expf(sScore[rbase + g]      - mx);
            float wb = __expf(sScore[rbase + g + 8]  - mx);
            float wc = __expf(sScore[rbase + g + 16] - mx);
            float wd = __expf(sScore[rbase + g + 24] - mx);
            float* sRed = tl ? sRed1 : sRed0;
#pragma unroll
            for (int nt = 0; nt < 8; ++nt) {
                int c0 = 8 * nt + 2 * t, c1 = c0 + 1;
                float b0 = sBias[64 + c0], b1 = sBias[64 + c1];
                float p0 = wa * rrelu(acc[0][nt][0] + b0) + wb * rrelu(acc[0][nt][2] + b0)
                         + wc * rrelu(acc[1][nt][0] + b0) + wd * rrelu(acc[1][nt][2] + b0);
                float p1 = wa * rrelu(acc[0][nt][1] + b1) + wb * rrelu(acc[0][nt][3] + b1)
                         + wc * rrelu(acc[1][nt][1] + b1) + wd * rrelu(acc[1][nt][3] + b1);
                p0 += __shfl_xor_sync(0xffffffffu, p0, 4);
                p0 += __shfl_xor_sync(0xffffffffu, p0, 8);
                p0 += __shfl_xor_sync(0xffffffffu, p0, 16);
                p1 += __shfl_xor_sync(0xffffffffu, p1, 4);
                p1 += __shfl_xor_sync(0xffffffffu, p1, 8);
                p1 += __shfl_xor_sync(0xffffffffu, p1, 16);
                if (g == 0) {
                    sRed[kw * 64 + c0] = p0;
                    sRed[kw * 64 + c1] = p1;
                }
            }
        }
        __syncthreads();
    }

    // ---- in-block two-tile logsumexp merge, write per-split partials ----
    float M = fmaxf(tm[0], tm[1]);
    float e0 = __expf(tm[0] - M);
    float e1 = __expf(tm[1] - M);   // 0 when ntiles==1 (tm[1]=-inf)
    if (tid < H_) {
        float A = (sRed0[tid] + sRed0[64 + tid] + sRed0[128 + tid] + sRed0[192 + tid]) * e0;
        if (ntiles == 2)
            A += (sRed1[tid] + sRed1[64 + tid] + sRed1[128 + tid] + sRed1[192 + tid]) * e1;
        g_acc[idx * H_ + tid] = A;
    }
    if (tid == 0) {
        g_m[idx] = M;
        g_s[idx] = tsum[0] * e0 + tsum[1] * e1;
    }

    // ---- last-block combine (threadfence reduction) ----
    __threadfence();
    __syncthreads();
    if (tid == 0) {
        int old = atomicAdd(&g_cnt[b], 1);
        *sLast = (old == nlive - 1);
    }
    __syncthreads();
    if (*sLast) {
        if (tid < H_) {
            volatile float* vm = g_m + b * NSPLIT;
            volatile float* vs = g_s + b * NSPLIT;
            volatile float* va = g_acc + (size_t)b * NSPLIT * H_;
            float MM = -INFINITY;
            for (int i = 0; i < nlive; ++i) MM = fmaxf(MM, vm[i]);
            float S = 0.f, A = 0.f;
            for (int i = 0; i < nlive; ++i) {
                float e = __expf(vm[i] - MM);
                S += vs[i] * e;
                A += va[i * H_ + tid] * e;
            }
            out[b * H_ + tid] = A / S;
        }
        if (tid == 0) g_cnt[b] = 0;   // reset for next replay
    }
}

// ---------------------------------------------------------------------------
extern "C" void kernel_launch(void* const* d_in, const int* in_sizes, int n_in,
                              void* d_out, int out_size) {
    const float* ts      = (const float*)d_in[0];
    const float* seq     = (const float*)d_in[1];
    const int*   lengths = (const int*)  d_in[2];
    const float* Wk      = (const float*)d_in[3];
    const float* bk      = (const float*)d_in[4];
    const float* Wq      = (const float*)d_in[5];
    const float* bq      = (const float*)d_in[6];
    const float* Wv      = (const float*)d_in[7];
    const float* bv      = (const float*)d_in[8];
    float* out = (float*)d_out;

    static int configured = 0;
    if (!configured) {
        cudaFuncSetAttribute(fused_attn,
                             cudaFuncAttributeMaxDynamicSharedMemorySize, SMEM_TOTAL);
        configured = 1;
    }

    dim3 grid(NSPLIT, B_);
    fused_attn<<<grid, TPB, SMEM_TOTAL>>>(ts, seq, lengths, Wk, bk, Wq, bq, Wv, bv, out);
}